// round 1
// baseline (speedup 1.0000x reference)
#include <cuda_runtime.h>
#include <math.h>

#define N 4096
#define BM 128
#define BN 128
#define BK 16
#define NSPLIT 8
#define JCHUNK (N / NSPLIT)   /* 512 */
#define NSUB (JCHUNK / BN)    /* 4   */

// ---------------- device scratch (no allocations allowed) ----------------
__device__ float g_cint[N];
__device__ float g_lacc[NSPLIT][N];
__device__ float g_uacc[NSPLIT][N];

// ---------------- packed f32x2 helpers (Blackwell FFMA2) -----------------
__device__ __forceinline__ void ffma2(unsigned long long &c,
                                      unsigned long long a,
                                      unsigned long long b) {
    asm("fma.rn.f32x2 %0, %1, %2, %0;" : "+l"(c) : "l"(a), "l"(b));
}
__device__ __forceinline__ unsigned long long dup2(float x) {
    unsigned long long r;
    asm("mov.b64 %0, {%1, %1};" : "=l"(r) : "f"(x));
    return r;
}
__device__ __forceinline__ void unpack2(unsigned long long v, float &lo, float &hi) {
    asm("mov.b64 {%0, %1}, %2;" : "=f"(lo), "=f"(hi) : "l"(v));
}

// ---------------- kernel: zero the whole output buffer -------------------
__global__ void k_zero(float4 *out, long n4) {
    long i = (long)blockIdx.x * blockDim.x + threadIdx.x;
    long stride = (long)gridDim.x * blockDim.x;
    float4 z = make_float4(0.f, 0.f, 0.f, 0.f);
    for (; i < n4; i += stride) out[i] = z;
}

// ---------------- kernel: cint = W2 @ b1 + b2 ----------------------------
__global__ void k_cint(const float *__restrict__ W2,
                       const float *__restrict__ b1,
                       const float *__restrict__ b2) {
    int row = blockIdx.x;
    __shared__ float sred[256];
    const float4 *w = (const float4 *)(W2 + (long)row * N);
    const float4 *bb = (const float4 *)b1;
    float s = 0.f;
    for (int c = threadIdx.x; c < N / 4; c += 256) {
        float4 wv = w[c], bv = bb[c];
        s += wv.x * bv.x + wv.y * bv.y + wv.z * bv.z + wv.w * bv.w;
    }
    sred[threadIdx.x] = s;
    __syncthreads();
    for (int off = 128; off > 0; off >>= 1) {
        if (threadIdx.x < off) sred[threadIdx.x] += sred[threadIdx.x + off];
        __syncthreads();
    }
    if (threadIdx.x == 0) g_cint[row] = sred[0] + b2[row];
}

// ---- kernel: M = W2@W1 tile-by-tile, fused pos/neg row reductions -------
// grid: (N/BM, NSPLIT).  Block (by, s) computes rows [by*BM, +BM) over
// columns [s*JCHUNK, +JCHUNK) and accumulates, per row i:
//   lacc[i] = sum_j M[i,j] * (M[i,j] > 0 ? lb0[j] : ub0[j])
//   uacc[i] = sum_j M[i,j] * (M[i,j] > 0 ? ub0[j] : lb0[j])
__global__ __launch_bounds__(256) void k_gemm_reduce(
    const float *__restrict__ W2, const float *__restrict__ W1,
    const float *__restrict__ lb0, const float *__restrict__ ub0) {

    __shared__ float As[BK][BM + 4];   // transposed W2 tile: As[k][m]
    __shared__ float Bs[BK][BN];       // W1 tile: Bs[k][n]
    __shared__ float red_l[BM][17];
    __shared__ float red_u[BM][17];
    __shared__ float rowacc_l[BM];
    __shared__ float rowacc_u[BM];

    const int tid = threadIdx.x;
    const int tx = tid & 15;
    const int ty = tid >> 4;
    const int by = blockIdx.x;
    const int split = blockIdx.y;
    const int i0 = by * BM;

    if (tid < BM) { rowacc_l[tid] = 0.f; rowacc_u[tid] = 0.f; }

    for (int jt = 0; jt < NSUB; ++jt) {
        const int j0 = split * JCHUNK + jt * BN;

        unsigned long long acc[8][4];
#pragma unroll
        for (int m = 0; m < 8; ++m)
#pragma unroll
            for (int p = 0; p < 4; ++p) acc[m][p] = 0ull;

        __syncthreads();  // previous jt's red/rowacc reads done; safe to reuse tiles

        for (int k0 = 0; k0 < N; k0 += BK) {
            // load W2 tile [BM x BK] transposed into As
#pragma unroll
            for (int l = 0; l < 2; ++l) {
                int lin = tid + l * 256;          // 0..511 float4s
                int r = lin >> 2;                 // row in tile
                int kc = (lin & 3) * 4;           // k column base
                float4 v = *(const float4 *)&W2[(long)(i0 + r) * N + k0 + kc];
                As[kc + 0][r] = v.x;
                As[kc + 1][r] = v.y;
                As[kc + 2][r] = v.z;
                As[kc + 3][r] = v.w;
            }
            // load W1 tile [BK x BN]
#pragma unroll
            for (int l = 0; l < 2; ++l) {
                int lin = tid + l * 256;
                int r = lin >> 5;                 // k row
                int c4 = (lin & 31) * 4;          // n column base
                *(float4 *)&Bs[r][c4] =
                    *(const float4 *)&W1[(long)(k0 + r) * N + j0 + c4];
            }
            __syncthreads();

#pragma unroll
            for (int kk = 0; kk < BK; ++kk) {
                float4 a0 = *(const float4 *)&As[kk][ty * 8];
                float4 a1 = *(const float4 *)&As[kk][ty * 8 + 4];
                float4 b0 = *(const float4 *)&Bs[kk][tx * 8];
                float4 b1v = *(const float4 *)&Bs[kk][tx * 8 + 4];
                unsigned long long bp[4];
                bp[0] = ((const unsigned long long *)&b0)[0];
                bp[1] = ((const unsigned long long *)&b0)[1];
                bp[2] = ((const unsigned long long *)&b1v)[0];
                bp[3] = ((const unsigned long long *)&b1v)[1];
                unsigned long long ap[8];
                ap[0] = dup2(a0.x); ap[1] = dup2(a0.y);
                ap[2] = dup2(a0.z); ap[3] = dup2(a0.w);
                ap[4] = dup2(a1.x); ap[5] = dup2(a1.y);
                ap[6] = dup2(a1.z); ap[7] = dup2(a1.w);
#pragma unroll
                for (int m = 0; m < 8; ++m)
#pragma unroll
                    for (int p = 0; p < 4; ++p) ffma2(acc[m][p], ap[m], bp[p]);
            }
            __syncthreads();
        }

        // ---- epilogue: select-and-reduce this BM x BN tile into row sums
        float lbv[8], ubv[8];
        {
            float4 l0 = *(const float4 *)&lb0[j0 + tx * 8];
            float4 l1 = *(const float4 *)&lb0[j0 + tx * 8 + 4];
            float4 u0 = *(const float4 *)&ub0[j0 + tx * 8];
            float4 u1 = *(const float4 *)&ub0[j0 + tx * 8 + 4];
            lbv[0] = l0.x; lbv[1] = l0.y; lbv[2] = l0.z; lbv[3] = l0.w;
            lbv[4] = l1.x; lbv[5] = l1.y; lbv[6] = l1.z; lbv[7] = l1.w;
            ubv[0] = u0.x; ubv[1] = u0.y; ubv[2] = u0.z; ubv[3] = u0.w;
            ubv[4] = u1.x; ubv[5] = u1.y; ubv[6] = u1.z; ubv[7] = u1.w;
        }
#pragma unroll
        for (int m = 0; m < 8; ++m) {
            float pl = 0.f, pu = 0.f;
#pragma unroll
            for (int p = 0; p < 4; ++p) {
                float mlo, mhi;
                unpack2(acc[m][p], mlo, mhi);
                int n0 = 2 * p, n1 = 2 * p + 1;
                pl += mlo * (mlo > 0.f ? lbv[n0] : ubv[n0]);
                pu += mlo * (mlo > 0.f ? ubv[n0] : lbv[n0]);
                pl += mhi * (mhi > 0.f ? lbv[n1] : ubv[n1]);
                pu += mhi * (mhi > 0.f ? ubv[n1] : lbv[n1]);
            }
            red_l[ty * 8 + m][tx] = pl;
            red_u[ty * 8 + m][tx] = pu;
        }
        __syncthreads();
        {
            int which = tid >> 7;       // 0 -> lower, 1 -> upper
            int row = tid & 127;
            float s = 0.f;
            if (which == 0) {
#pragma unroll
                for (int q = 0; q < 16; ++q) s += red_l[row][q];
                rowacc_l[row] += s;
            } else {
#pragma unroll
                for (int q = 0; q < 16; ++q) s += red_u[row][q];
                rowacc_u[row] += s;
            }
        }
    }
    __syncthreads();
    if (tid < BM) {
        g_lacc[split][i0 + tid] = rowacc_l[tid];
        g_uacc[split][i0 + tid] = rowacc_u[tid];
    }
}

// ---------------- kernel: DeepPoly ReLU transformer + scatter ------------
__global__ void k_finalize(const float *__restrict__ raw_alpha,
                           float *__restrict__ out) {
    int i = blockIdx.x * blockDim.x + threadIdx.x;
    if (i >= N) return;
    float lb = g_cint[i], ub = g_cint[i];
#pragma unroll
    for (int s = 0; s < NSPLIT; ++s) {
        lb += g_lacc[s][i];
        ub += g_uacc[s][i];
    }
    float denom = ub - lb;
    float rs = (denom == 0.f) ? 0.f : ub / denom;
    float rint = (1.f - rs) * ub;
    bool below = (ub <= 0.f);
    bool above = (lb >= 0.f);
    bool crossing = !(below || above);
    float base = above ? 1.f : 0.f;
    float uslope = crossing ? rs : base;
    float uint_ = crossing ? rint : 0.f;
    float v1 = crossing ? 0.f : base;
    float v2 = crossing ? 1.f : base;
    float alpha = 1.f / (1.f + expf(-raw_alpha[i]));
    float lslope = alpha * v1 + (1.f - alpha) * v2;

    const long NN = (long)N * N;
    out[(long)i * N + i] = lslope;               // diag(lslope)  [0, NN)
    /* lintercept [NN, NN+N) stays zero */
    out[NN + N + (long)i * N + i] = uslope;      // diag(uslope)
    out[2 * NN + N + i] = uint_;                 // uintercept
}

// --------------------------------------------------------------------------
extern "C" void kernel_launch(void *const *d_in, const int *in_sizes, int n_in,
                              void *d_out, int out_size) {
    const float *raw_alpha = (const float *)d_in[0];
    const float *lb0 = (const float *)d_in[1];
    const float *ub0 = (const float *)d_in[2];
    const float *W1 = (const float *)d_in[3];
    const float *b1 = (const float *)d_in[4];
    const float *W2 = (const float *)d_in[5];
    const float *b2 = (const float *)d_in[6];
    float *out = (float *)d_out;

    k_zero<<<2048, 256>>>((float4 *)out, (long)out_size / 4);
    k_cint<<<N, 256>>>(W2, b1, b2);
    dim3 g(N / BM, NSPLIT);
    k_gemm_reduce<<<g, 256>>>(W2, W1, lb0, ub0);
    k_finalize<<<N / 256, 256>>>(raw_alpha, out);
}

// round 3
// speedup vs baseline: 4.4243x; 4.4243x over previous
#include <cuda_runtime.h>
#include <math.h>
#include <stdint.h>

#define N 4096
#define NSTAGE 128            /* K / 32 */

// ---------------- device scratch (no allocations allowed) ----------------
// A image: W2 RNA-rounded, fragment order [mt 0..255][kt 0..511][lane 32][4]
__device__ float g_A[(size_t)256 * 512 * 128];
// B image: W1 RNA-rounded, fragment order [nt 0..511][kt 0..511][lane 32][2]
__device__ float g_B[(size_t)512 * 512 * 64];
__device__ float g_t[N];          // W1 @ c
__device__ float g_mc[N];         // W2 @ t
__device__ float g_cint[N];       // W2 @ b1 + b2
__device__ float g_rpart[32][N];  // per-nb partial of sum_j |M_ij| h_j

// ---------------- helpers ----------------
__device__ __forceinline__ uint32_t smem_u32(const void *p) {
    uint32_t a;
    asm("{ .reg .u64 t; cvta.to.shared.u64 t, %1; cvt.u32.u64 %0, t; }" : "=r"(a) : "l"(p));
    return a;
}
__device__ __forceinline__ float rna_tf32(float x) {
    uint32_t u;
    asm("cvt.rna.tf32.f32 %0, %1;" : "=r"(u) : "f"(x));
    return __uint_as_float(u);
}
__device__ __forceinline__ void cpasync16(uint32_t dst, const void *src) {
    asm volatile("cp.async.cg.shared.global [%0], [%1], 16;" :: "r"(dst), "l"(src) : "memory");
}
__device__ __forceinline__ void lds128(uint32_t *r, uint32_t a) {
    asm volatile("ld.shared.v4.b32 {%0,%1,%2,%3}, [%4];"
                 : "=r"(r[0]), "=r"(r[1]), "=r"(r[2]), "=r"(r[3]) : "r"(a));
}
__device__ __forceinline__ void lds64(uint32_t *r, uint32_t a) {
    asm volatile("ld.shared.v2.b32 {%0,%1}, [%2];" : "=r"(r[0]), "=r"(r[1]) : "r"(a));
}
__device__ __forceinline__ void mma8(float *d, const uint32_t *a, const uint32_t *b) {
    asm volatile(
        "mma.sync.aligned.m16n8k8.row.col.f32.tf32.tf32.f32 "
        "{%0,%1,%2,%3}, {%4,%5,%6,%7}, {%8,%9}, {%0,%1,%2,%3};"
        : "+f"(d[0]), "+f"(d[1]), "+f"(d[2]), "+f"(d[3])
        : "r"(a[0]), "r"(a[1]), "r"(a[2]), "r"(a[3]), "r"(b[0]), "r"(b[1]));
}

// ---------------- kernel: zero the output buffer -------------------------
__global__ void k_zero(float4 *out, long n4) {
    long i = (long)blockIdx.x * blockDim.x + threadIdx.x;
    long stride = (long)gridDim.x * blockDim.x;
    float4 z = make_float4(0.f, 0.f, 0.f, 0.f);
    for (; i < n4; i += stride) out[i] = z;
}

// ---------------- preprocess W2 -> fragment-ordered tf32 image -----------
// grid: (256 mt) x (8 kg);  block handles 16 rows x 512 k-cols
__global__ __launch_bounds__(256) void k_preA(const float *__restrict__ W2) {
    __shared__ float s[16][512];
    int mt = blockIdx.x, kg = blockIdx.y, tid = threadIdx.x;
    for (int i = tid; i < 2048; i += 256) {
        int row = i >> 7, c4 = (i & 127) * 4;
        *(float4 *)&s[row][c4] =
            *(const float4 *)&W2[(size_t)(mt * 16 + row) * N + kg * 512 + c4];
    }
    __syncthreads();
    size_t base = ((size_t)mt * 512 + kg * 64) * 128;
    for (int o = tid; o < 8192; o += 256) {
        int kt = o >> 7, l = (o >> 2) & 31, r = o & 3;
        int row = (l >> 2) + (r & 1) * 8;
        int col = kt * 8 + (l & 3) + (r >> 1) * 4;
        g_A[base + o] = rna_tf32(s[row][col]);
    }
}

// ---------------- preprocess W1 -> fragment-ordered tf32 image -----------
// grid: (128 kg of 32 k-rows) x (16 ng of 256 n-cols)
__global__ __launch_bounds__(256) void k_preB(const float *__restrict__ W1) {
    __shared__ float s[32][256];
    int kg = blockIdx.x, ng = blockIdx.y, tid = threadIdx.x;
    for (int i = tid; i < 2048; i += 256) {
        int row = i >> 6, c4 = (i & 63) * 4;
        *(float4 *)&s[row][c4] =
            *(const float4 *)&W1[(size_t)(kg * 32 + row) * N + ng * 256 + c4];
    }
    __syncthreads();
    for (int o = tid; o < 8192; o += 256) {
        int nt = o >> 8, kt = (o >> 6) & 3, l = (o >> 1) & 31, r = o & 1;
        int k = kt * 8 + (l & 3) + r * 4;
        int n = nt * 8 + (l >> 2);
        g_B[(((size_t)(ng * 32 + nt)) * 512 + kg * 4 + kt) * 64 + l * 2 + r] =
            rna_tf32(s[k][n]);
    }
}

// ---------------- matvec: t = W1 @ c,  c = (lb0+ub0)/2 -------------------
__global__ void k_t(const float *__restrict__ W1, const float *__restrict__ lb0,
                    const float *__restrict__ ub0) {
    int row = blockIdx.x;
    __shared__ float sred[256];
    const float4 *w = (const float4 *)(W1 + (size_t)row * N);
    const float4 *l4 = (const float4 *)lb0;
    const float4 *u4 = (const float4 *)ub0;
    float s = 0.f;
    for (int c = threadIdx.x; c < N / 4; c += 256) {
        float4 wv = w[c], lv = l4[c], uv = u4[c];
        s += wv.x * (0.5f * (lv.x + uv.x)) + wv.y * (0.5f * (lv.y + uv.y)) +
             wv.z * (0.5f * (lv.z + uv.z)) + wv.w * (0.5f * (lv.w + uv.w));
    }
    sred[threadIdx.x] = s;
    __syncthreads();
    for (int off = 128; off > 0; off >>= 1) {
        if (threadIdx.x < off) sred[threadIdx.x] += sred[threadIdx.x + off];
        __syncthreads();
    }
    if (threadIdx.x == 0) g_t[row] = sred[0];
}

// ---------------- matvec: mc = W2 @ t ; cint = W2 @ b1 + b2 --------------
__global__ void k_w2(const float *__restrict__ W2, const float *__restrict__ b1,
                     const float *__restrict__ b2) {
    int row = blockIdx.x;
    __shared__ float sred[512];
    const float4 *w = (const float4 *)(W2 + (size_t)row * N);
    const float4 *t4 = (const float4 *)g_t;
    const float4 *b4 = (const float4 *)b1;
    float s0 = 0.f, s1 = 0.f;
    for (int c = threadIdx.x; c < N / 4; c += 256) {
        float4 wv = w[c], tv = t4[c], bv = b4[c];
        s0 += wv.x * tv.x + wv.y * tv.y + wv.z * tv.z + wv.w * tv.w;
        s1 += wv.x * bv.x + wv.y * bv.y + wv.z * bv.z + wv.w * bv.w;
    }
    sred[threadIdx.x] = s0;
    sred[256 + threadIdx.x] = s1;
    __syncthreads();
    for (int off = 128; off > 0; off >>= 1) {
        if (threadIdx.x < off) {
            sred[threadIdx.x] += sred[threadIdx.x + off];
            sred[256 + threadIdx.x] += sred[256 + threadIdx.x + off];
        }
        __syncthreads();
    }
    if (threadIdx.x == 0) {
        g_mc[row] = sred[0];
        g_cint[row] = sred[256] + b2[row];
    }
}

// ---------------- main GEMM: r = rowsum(|W2@W1| * h) via tf32 mma.sync ---
#define GS_A0 0
#define GS_B0 16384
#define GS_A1 32768
#define GS_B1 49152
#define GS_H  65536
#define GS_RED 66048
#define GSMEM 68096

__device__ __forceinline__ void issue_stage(int s, int mb, int nb,
                                            uint32_t sA, uint32_t sB, int tid) {
    int mt = tid >> 5, ia = tid & 31;
    const float *srcA = &g_A[((size_t)(mb * 8 + mt) * 512 + s * 4) * 128];
    uint32_t dA = sA + mt * 2048;
#pragma unroll
    for (int r = 0; r < 4; ++r)
        cpasync16(dA + (r * 32 + ia) * 16, srcA + (r * 32 + ia) * 4);
    int nt = tid >> 4, ib = tid & 15;
    const float *srcB = &g_B[((size_t)(nb * 16 + nt) * 512 + s * 4) * 64];
    uint32_t dB = sB + nt * 1024;
#pragma unroll
    for (int r = 0; r < 4; ++r)
        cpasync16(dB + (r * 16 + ib) * 16, srcB + (r * 16 + ib) * 4);
    asm volatile("cp.async.commit_group;" ::: "memory");
}

__global__ __launch_bounds__(256) void k_gemm(const float *__restrict__ lb0,
                                              const float *__restrict__ ub0) {
    extern __shared__ char sm[];
    uint32_t sb = smem_u32(sm);
    const int tid = threadIdx.x, lane = tid & 31, wid = tid >> 5;
    const int wn = wid & 3, wm = wid >> 2;
    const int nb = blockIdx.x, mb = blockIdx.y;
    float *h = (float *)(sm + GS_H);
    float *red = (float *)(sm + GS_RED);
    if (tid < 128) h[tid] = 0.5f * (ub0[nb * 128 + tid] - lb0[nb * 128 + tid]);

    float acc[4][4][4];
#pragma unroll
    for (int a = 0; a < 4; ++a)
#pragma unroll
        for (int b = 0; b < 4; ++b)
#pragma unroll
            for (int c = 0; c < 4; ++c) acc[a][b][c] = 0.f;

    const uint32_t sAb[2] = {sb + GS_A0, sb + GS_A1};
    const uint32_t sBb[2] = {sb + GS_B0, sb + GS_B1};

    issue_stage(0, mb, nb, sAb[0], sBb[0], tid);

    for (int s = 0; s < NSTAGE; ++s) {
        if (s + 1 < NSTAGE) {
            issue_stage(s + 1, mb, nb, sAb[(s + 1) & 1], sBb[(s + 1) & 1], tid);
            asm volatile("cp.async.wait_group 1;" ::: "memory");
        } else {
            asm volatile("cp.async.wait_group 0;" ::: "memory");
        }
        __syncthreads();
        uint32_t aBase = sAb[s & 1], bBase = sBb[s & 1];
#pragma unroll
        for (int kk = 0; kk < 4; ++kk) {
            uint32_t af[4][4], bf[4][2];
#pragma unroll
            for (int mt = 0; mt < 4; ++mt)
                lds128(af[mt], aBase + (((wm * 4 + mt) * 4 + kk) * 32 + lane) * 16);
#pragma unroll
            for (int nt = 0; nt < 4; ++nt)
                lds64(bf[nt], bBase + (((wn * 4 + nt) * 4 + kk) * 32 + lane) * 8);
#pragma unroll
            for (int mt = 0; mt < 4; ++mt)
#pragma unroll
                for (int nt = 0; nt < 4; ++nt)
                    mma8(acc[mt][nt], af[mt], bf[nt]);
        }
        __syncthreads();
    }

    // epilogue: weighted abs row-reduction
    const int tig = lane & 3, gp = lane >> 2;
#pragma unroll
    for (int mt = 0; mt < 4; ++mt)
#pragma unroll
        for (int hf = 0; hf < 2; ++hf) {
            float p = 0.f;
#pragma unroll
            for (int nt = 0; nt < 4; ++nt) {
                int n0 = wn * 32 + nt * 8 + 2 * tig;
                p += fabsf(acc[mt][nt][hf * 2 + 0]) * h[n0] +
                     fabsf(acc[mt][nt][hf * 2 + 1]) * h[n0 + 1];
            }
            p += __shfl_xor_sync(0xffffffffu, p, 1);
            p += __shfl_xor_sync(0xffffffffu, p, 2);
            if (tig == 0)
                red[(wm * 64 + mt * 16 + hf * 8 + gp) * 4 + wn] = p;
        }
    __syncthreads();
    if (tid < 128) {
        float v = red[tid * 4 + 0] + red[tid * 4 + 1] + red[tid * 4 + 2] + red[tid * 4 + 3];
        g_rpart[nb][mb * 128 + tid] = v;
    }
}

// ---------------- finalize: DeepPoly ReLU transformer + scatter ----------
__global__ void k_finalize(const float *__restrict__ raw_alpha,
                           float *__restrict__ out) {
    int i = blockIdx.x * blockDim.x + threadIdx.x;
    if (i >= N) return;
    float r = 0.f;
#pragma unroll
    for (int s = 0; s < 32; ++s) r += g_rpart[s][i];
    float mid = g_mc[i] + g_cint[i];
    float lb = mid - r;
    float ub = mid + r;
    float denom = ub - lb;
    float rs = (denom == 0.f) ? 0.f : ub / denom;
    float rint = (1.f - rs) * ub;
    bool below = (ub <= 0.f);
    bool above = (lb >= 0.f);
    bool crossing = !(below || above);
    float base = above ? 1.f : 0.f;
    float uslope = crossing ? rs : base;
    float uint_ = crossing ? rint : 0.f;
    float v1 = crossing ? 0.f : base;
    float v2 = crossing ? 1.f : base;
    float alpha = 1.f / (1.f + expf(-raw_alpha[i]));
    float lslope = alpha * v1 + (1.f - alpha) * v2;

    const long NN = (long)N * N;
    out[(long)i * N + i] = lslope;               // diag(lslope)
    /* lintercept stays zero */
    out[NN + N + (long)i * N + i] = uslope;      // diag(uslope)
    out[2 * NN + N + i] = uint_;                 // uintercept
}

// --------------------------------------------------------------------------
extern "C" void kernel_launch(void *const *d_in, const int *in_sizes, int n_in,
                              void *d_out, int out_size) {
    const float *raw_alpha = (const float *)d_in[0];
    const float *lb0 = (const float *)d_in[1];
    const float *ub0 = (const float *)d_in[2];
    const float *W1 = (const float *)d_in[3];
    const float *b1 = (const float *)d_in[4];
    const float *W2 = (const float *)d_in[5];
    const float *b2 = (const float *)d_in[6];
    float *out = (float *)d_out;

    cudaFuncSetAttribute(k_gemm, cudaFuncAttributeMaxDynamicSharedMemorySize, GSMEM);

    k_zero<<<2048, 256>>>((float4 *)out, (long)out_size / 4);
    dim3 ga(256, 8);
    k_preA<<<ga, 256>>>(W2);
    dim3 gb(128, 16);
    k_preB<<<gb, 256>>>(W1);
    k_t<<<N, 256>>>(W1, lb0, ub0);
    k_w2<<<N, 256>>>(W2, b1, b2);
    dim3 gg(32, 32);
    k_gemm<<<gg, 256, GSMEM>>>(lb0, ub0);
    k_finalize<<<N / 256, 256>>>(raw_alpha, out);
}

// round 4
// speedup vs baseline: 6.4310x; 1.4536x over previous
#include <cuda_runtime.h>
#include <cuda_fp16.h>
#include <math.h>
#include <stdint.h>

#define N 4096
#define NSTAGE 128            /* K / 32 */

// ---------------- device scratch (no allocations allowed) ----------------
// A image: W2 fp16, m16n8k16 fragment order [mt 0..255][ktile 0..255][lane][4 regs]
__device__ uint32_t g_A[(size_t)256 * 256 * 32 * 4];   // 32 MB
// B image: W1 fp16, fragment order [nt 0..511][ktile 0..255][lane][2 regs]
__device__ uint32_t g_B[(size_t)512 * 256 * 32 * 2];   // 32 MB
__device__ float g_tpart[16][N];   // partial W1 @ c  (per ng)
__device__ float g_t[N];           // W1 @ c
__device__ float g_mcpart[8][N];   // partial W2 @ t  (per kg)
__device__ float g_cipart[8][N];   // partial W2 @ b1 (per kg)
__device__ float g_rpart[32][N];   // per-nb partial of sum_j |M_ij| h_j

// ---------------- helpers ----------------
__device__ __forceinline__ uint32_t smem_u32(const void *p) {
    uint32_t a;
    asm("{ .reg .u64 t; cvta.to.shared.u64 t, %1; cvt.u32.u64 %0, t; }" : "=r"(a) : "l"(p));
    return a;
}
__device__ __forceinline__ void cpasync16(uint32_t dst, const void *src) {
    asm volatile("cp.async.cg.shared.global [%0], [%1], 16;" :: "r"(dst), "l"(src) : "memory");
}
__device__ __forceinline__ void lds128(uint32_t *r, uint32_t a) {
    asm volatile("ld.shared.v4.b32 {%0,%1,%2,%3}, [%4];"
                 : "=r"(r[0]), "=r"(r[1]), "=r"(r[2]), "=r"(r[3]) : "r"(a));
}
__device__ __forceinline__ void lds64(uint32_t *r, uint32_t a) {
    asm volatile("ld.shared.v2.b32 {%0,%1}, [%2];" : "=r"(r[0]), "=r"(r[1]) : "r"(a));
}
__device__ __forceinline__ void mma16(float *d, const uint32_t *a, const uint32_t *b) {
    asm volatile(
        "mma.sync.aligned.m16n8k16.row.col.f32.f16.f16.f32 "
        "{%0,%1,%2,%3}, {%4,%5,%6,%7}, {%8,%9}, {%0,%1,%2,%3};"
        : "+f"(d[0]), "+f"(d[1]), "+f"(d[2]), "+f"(d[3])
        : "r"(a[0]), "r"(a[1]), "r"(a[2]), "r"(a[3]), "r"(b[0]), "r"(b[1]));
}
__device__ __forceinline__ uint32_t pack_h2(float lo, float hi) {
    __half2 h = __halves2half2(__float2half_rn(lo), __float2half_rn(hi));
    return *(uint32_t *)&h;
}

// ---------------- kernel: zero the output buffer -------------------------
__global__ void k_zero(float4 *out, long n4) {
    long i = (long)blockIdx.x * blockDim.x + threadIdx.x;
    long stride = (long)gridDim.x * blockDim.x;
    float4 z = make_float4(0.f, 0.f, 0.f, 0.f);
    for (; i < n4; i += stride) out[i] = z;
}

// ---- preprocess W1 -> fp16 fragment image  +  partial t = W1 @ c --------
// grid: (128 kg of 32 k-rows) x (16 ng of 256 n-cols)
__global__ __launch_bounds__(256) void k_preB(const float *__restrict__ W1,
                                              const float *__restrict__ lb0,
                                              const float *__restrict__ ub0) {
    __shared__ float s[32][256];
    int kg = blockIdx.x, ng = blockIdx.y, tid = threadIdx.x;
    for (int i = tid; i < 2048; i += 256) {
        int row = i >> 6, c4 = (i & 63) * 4;
        *(float4 *)&s[row][c4] =
            *(const float4 *)&W1[(size_t)(kg * 32 + row) * N + ng * 256 + c4];
    }
    __syncthreads();
    // fragment writes: 4096 u32 per block
#pragma unroll
    for (int it = 0; it < 16; ++it) {
        int o = tid + it * 256;
        int nt_local = o >> 7;
        int rem = o & 127;
        int kt_local = rem >> 6;
        int lane = (rem >> 1) & 31;
        int reg = rem & 1;
        int g = lane >> 2, t4 = lane & 3;
        int k0 = kt_local * 16 + 2 * t4 + reg * 8;
        int n = nt_local * 8 + g;
        uint32_t v = pack_h2(s[k0][n], s[k0 + 1][n]);
        size_t nt_g = ng * 32 + nt_local;
        size_t kt_g = kg * 2 + kt_local;
        g_B[((nt_g * 256 + kt_g) * 32 + lane) * 2 + reg] = v;
    }
    // fused partial t = W1 @ c over this block's tile
    {
        int r = tid >> 3, q = tid & 7;
        float sum = 0.f;
#pragma unroll
        for (int c = 0; c < 32; ++c) {
            int j = ng * 256 + q * 32 + c;
            sum += s[r][q * 32 + c] * (0.5f * (lb0[j] + ub0[j]));
        }
        sum += __shfl_xor_sync(0xffffffffu, sum, 1);
        sum += __shfl_xor_sync(0xffffffffu, sum, 2);
        sum += __shfl_xor_sync(0xffffffffu, sum, 4);
        if (q == 0) g_tpart[ng][kg * 32 + r] = sum;
    }
}

// ---------------- reduce t partials ----------------
__global__ void k_redt(void) {
    int i = blockIdx.x * blockDim.x + threadIdx.x;
    float s = 0.f;
#pragma unroll
    for (int ng = 0; ng < 16; ++ng) s += g_tpart[ng][i];
    g_t[i] = s;
}

// ---- preprocess W2 -> fp16 fragment image + partial W2@t, W2@b1 ---------
// grid: (256 mt of 16 rows) x (8 kg of 512 cols)
__global__ __launch_bounds__(256) void k_preA(const float *__restrict__ W2,
                                              const float *__restrict__ b1) {
    __shared__ float s[16][512];
    int mt = blockIdx.x, kg = blockIdx.y, tid = threadIdx.x;
    for (int i = tid; i < 2048; i += 256) {
        int row = i >> 7, c4 = (i & 127) * 4;
        *(float4 *)&s[row][c4] =
            *(const float4 *)&W2[(size_t)(mt * 16 + row) * N + kg * 512 + c4];
    }
    __syncthreads();
    // fragment writes: 4096 u32 per block
#pragma unroll
    for (int it = 0; it < 16; ++it) {
        int o = tid + it * 256;
        int ktile_local = o >> 7;          // 0..31
        int rem = o & 127;
        int lane = rem >> 2;
        int reg = rem & 3;
        int g = lane >> 2, t4 = lane & 3;
        int row = g + (reg & 1) * 8;
        int c0 = ktile_local * 16 + 2 * t4 + (reg >> 1) * 8;
        uint32_t v = pack_h2(s[row][c0], s[row][c0 + 1]);
        size_t kt_g = kg * 32 + ktile_local;
        g_A[(((size_t)mt * 256 + kt_g) * 32 + lane) * 4 + reg] = v;
    }
    // fused partial mc = W2 @ t and ci = W2 @ b1
    {
        int row = tid >> 4, q = tid & 15;
        float s0 = 0.f, s1 = 0.f;
#pragma unroll
        for (int c = 0; c < 32; ++c) {
            int j = kg * 512 + q * 32 + c;
            float w = s[row][q * 32 + c];
            s0 += w * g_t[j];
            s1 += w * b1[j];
        }
#pragma unroll
        for (int m = 1; m < 16; m <<= 1) {
            s0 += __shfl_xor_sync(0xffffffffu, s0, m);
            s1 += __shfl_xor_sync(0xffffffffu, s1, m);
        }
        if (q == 0) {
            g_mcpart[kg][mt * 16 + row] = s0;
            g_cipart[kg][mt * 16 + row] = s1;
        }
    }
}

// ---------------- main GEMM: r = rowsum(|W2@W1| * h), fp16 mma.sync ------
#define GS_A0 0
#define GS_B0 8192
#define GS_A1 16384
#define GS_B1 24576
#define GS_H  32768
#define GS_RED 33280
#define GSMEM 35328

__device__ __forceinline__ void issue_stage(int s, int mb, int nb,
                                            uint32_t sA, uint32_t sB, int tid) {
    // A: 8 mt tiles, 1KB each (2 ktiles)
    int mt = tid >> 5, ia = tid & 31;
    const uint32_t *srcA = &g_A[(((size_t)(mb * 8 + mt) * 256 + s * 2) * 32) * 4];
    uint32_t dA = sA + mt * 1024;
#pragma unroll
    for (int r = 0; r < 2; ++r)
        cpasync16(dA + (r * 32 + ia) * 16, srcA + (r * 32 + ia) * 4);
    // B: 16 nt tiles, 512B each (2 ktiles)
    int nt = tid >> 4, ib = tid & 15;
    const uint32_t *srcB = &g_B[(((size_t)(nb * 16 + nt) * 256 + s * 2) * 32) * 2];
    uint32_t dB = sB + nt * 512;
#pragma unroll
    for (int r = 0; r < 2; ++r)
        cpasync16(dB + (r * 16 + ib) * 16, srcB + (r * 16 + ib) * 4);
    asm volatile("cp.async.commit_group;" ::: "memory");
}

__global__ __launch_bounds__(256) void k_gemm(const float *__restrict__ lb0,
                                              const float *__restrict__ ub0) {
    __shared__ __align__(16) char sm[GSMEM];
    uint32_t sb = smem_u32(sm);
    const int tid = threadIdx.x, lane = tid & 31, wid = tid >> 5;
    const int wn = wid & 3, wm = wid >> 2;
    const int nb = blockIdx.x, mb = blockIdx.y;
    float *h = (float *)(sm + GS_H);
    float *red = (float *)(sm + GS_RED);
    if (tid < 128) h[tid] = 0.5f * (ub0[nb * 128 + tid] - lb0[nb * 128 + tid]);

    float acc[4][4][4];
#pragma unroll
    for (int a = 0; a < 4; ++a)
#pragma unroll
        for (int b = 0; b < 4; ++b)
#pragma unroll
            for (int c = 0; c < 4; ++c) acc[a][b][c] = 0.f;

    const uint32_t sAb[2] = {sb + GS_A0, sb + GS_A1};
    const uint32_t sBb[2] = {sb + GS_B0, sb + GS_B1};

    issue_stage(0, mb, nb, sAb[0], sBb[0], tid);

    for (int s = 0; s < NSTAGE; ++s) {
        if (s + 1 < NSTAGE) {
            issue_stage(s + 1, mb, nb, sAb[(s + 1) & 1], sBb[(s + 1) & 1], tid);
            asm volatile("cp.async.wait_group 1;" ::: "memory");
        } else {
            asm volatile("cp.async.wait_group 0;" ::: "memory");
        }
        __syncthreads();
        uint32_t aBase = sAb[s & 1], bBase = sBb[s & 1];
#pragma unroll
        for (int kk = 0; kk < 2; ++kk) {
            uint32_t af[4][4], bf[4][2];
#pragma unroll
            for (int mt = 0; mt < 4; ++mt)
                lds128(af[mt], aBase + (((wm * 4 + mt) * 2 + kk) * 32 + lane) * 16);
#pragma unroll
            for (int nt = 0; nt < 4; ++nt)
                lds64(bf[nt], bBase + (((wn * 4 + nt) * 2 + kk) * 32 + lane) * 8);
#pragma unroll
            for (int mt = 0; mt < 4; ++mt)
#pragma unroll
                for (int nt = 0; nt < 4; ++nt)
                    mma16(acc[mt][nt], af[mt], bf[nt]);
        }
        __syncthreads();
    }

    // epilogue: weighted abs row-reduction
    const int tig = lane & 3, gp = lane >> 2;
#pragma unroll
    for (int mt = 0; mt < 4; ++mt)
#pragma unroll
        for (int hf = 0; hf < 2; ++hf) {
            float p = 0.f;
#pragma unroll
            for (int nt = 0; nt < 4; ++nt) {
                int n0 = wn * 32 + nt * 8 + 2 * tig;
                p += fabsf(acc[mt][nt][hf * 2 + 0]) * h[n0] +
                     fabsf(acc[mt][nt][hf * 2 + 1]) * h[n0 + 1];
            }
            p += __shfl_xor_sync(0xffffffffu, p, 1);
            p += __shfl_xor_sync(0xffffffffu, p, 2);
            if (tig == 0)
                red[(wm * 64 + mt * 16 + hf * 8 + gp) * 4 + wn] = p;
        }
    __syncthreads();
    if (tid < 128) {
        float v = red[tid * 4 + 0] + red[tid * 4 + 1] + red[tid * 4 + 2] + red[tid * 4 + 3];
        g_rpart[nb][mb * 128 + tid] = v;
    }
}

// ---------------- finalize: DeepPoly ReLU transformer + scatter ----------
__global__ void k_finalize(const float *__restrict__ raw_alpha,
                           const float *__restrict__ b2,
                           float *__restrict__ out) {
    int i = blockIdx.x * blockDim.x + threadIdx.x;
    if (i >= N) return;
    float r = 0.f;
#pragma unroll
    for (int s = 0; s < 32; ++s) r += g_rpart[s][i];
    float mid = b2[i];
#pragma unroll
    for (int s = 0; s < 8; ++s) mid += g_mcpart[s][i] + g_cipart[s][i];
    float lb = mid - r;
    float ub = mid + r;
    float denom = ub - lb;
    float rs = (denom == 0.f) ? 0.f : ub / denom;
    float rint = (1.f - rs) * ub;
    bool below = (ub <= 0.f);
    bool above = (lb >= 0.f);
    bool crossing = !(below || above);
    float base = above ? 1.f : 0.f;
    float uslope = crossing ? rs : base;
    float uint_ = crossing ? rint : 0.f;
    float v1 = crossing ? 0.f : base;
    float v2 = crossing ? 1.f : base;
    float alpha = 1.f / (1.f + expf(-raw_alpha[i]));
    float lslope = alpha * v1 + (1.f - alpha) * v2;

    const long NN = (long)N * N;
    out[(long)i * N + i] = lslope;               // diag(lslope)
    /* lintercept stays zero */
    out[NN + N + (long)i * N + i] = uslope;      // diag(uslope)
    out[2 * NN + N + i] = uint_;                 // uintercept
}

// --------------------------------------------------------------------------
extern "C" void kernel_launch(void *const *d_in, const int *in_sizes, int n_in,
                              void *d_out, int out_size) {
    const float *raw_alpha = (const float *)d_in[0];
    const float *lb0 = (const float *)d_in[1];
    const float *ub0 = (const float *)d_in[2];
    const float *W1 = (const float *)d_in[3];
    const float *b1 = (const float *)d_in[4];
    const float *W2 = (const float *)d_in[5];
    const float *b2 = (const float *)d_in[6];
    float *out = (float *)d_out;

    k_zero<<<2048, 256>>>((float4 *)out, (long)out_size / 4);
    dim3 gb(128, 16);
    k_preB<<<gb, 256>>>(W1, lb0, ub0);
    k_redt<<<16, 256>>>();
    dim3 ga(256, 8);
    k_preA<<<ga, 256>>>(W2, b1);
    dim3 gg(32, 32);
    k_gemm<<<gg, 256>>>(lb0, ub0);
    k_finalize<<<N / 256, 256>>>(raw_alpha, b2, out);
}

// round 5
// speedup vs baseline: 8.0802x; 1.2564x over previous
#include <cuda_runtime.h>
#include <cuda_fp16.h>
#include <math.h>
#include <stdint.h>

#define N 4096
#define NSTG 64               /* K / 64 */

// ---------------- device scratch (no allocations allowed) ----------------
// A image: W2 fp16, m16n8k16 fragment order [mt 0..255][ktile 0..255][lane][4]
__device__ uint32_t g_A[(size_t)256 * 256 * 32 * 4];   // 32 MB
// B image: W1 fp16, fragment order [nt 0..511][ktile 0..255][lane][2]
__device__ uint32_t g_B[(size_t)512 * 256 * 32 * 2];   // 32 MB
__device__ float g_t[N];           // W1 @ c
__device__ float g_mc[N];          // W2 @ t
__device__ float g_cint[N];        // W2 @ b1 + b2
__device__ float g_rpart[32][N];   // per-nb partial of sum_j |M_ij| h_j

// ---------------- helpers ----------------
__device__ __forceinline__ uint32_t smem_u32(const void *p) {
    uint32_t a;
    asm("{ .reg .u64 t; cvta.to.shared.u64 t, %1; cvt.u32.u64 %0, t; }" : "=r"(a) : "l"(p));
    return a;
}
__device__ __forceinline__ void cpasync16(uint32_t dst, const void *src) {
    asm volatile("cp.async.cg.shared.global [%0], [%1], 16;" :: "r"(dst), "l"(src) : "memory");
}
__device__ __forceinline__ void lds128(uint32_t *r, uint32_t a) {
    asm volatile("ld.shared.v4.b32 {%0,%1,%2,%3}, [%4];"
                 : "=r"(r[0]), "=r"(r[1]), "=r"(r[2]), "=r"(r[3]) : "r"(a));
}
__device__ __forceinline__ void lds64(uint32_t *r, uint32_t a) {
    asm volatile("ld.shared.v2.b32 {%0,%1}, [%2];" : "=r"(r[0]), "=r"(r[1]) : "r"(a));
}
__device__ __forceinline__ void mma16(float *d, const uint32_t *a, const uint32_t *b) {
    asm volatile(
        "mma.sync.aligned.m16n8k16.row.col.f32.f16.f16.f32 "
        "{%0,%1,%2,%3}, {%4,%5,%6,%7}, {%8,%9}, {%0,%1,%2,%3};"
        : "+f"(d[0]), "+f"(d[1]), "+f"(d[2]), "+f"(d[3])
        : "r"(a[0]), "r"(a[1]), "r"(a[2]), "r"(a[3]), "r"(b[0]), "r"(b[1]));
}
__device__ __forceinline__ uint32_t pack_h2(float lo, float hi) {
    __half2 h = __halves2half2(__float2half_rn(lo), __float2half_rn(hi));
    return *(uint32_t *)&h;
}

// ---------------- kernel: zero the output buffer -------------------------
__global__ void k_zero(float4 *out, long n4) {
    long i = (long)blockIdx.x * blockDim.x + threadIdx.x;
    long stride = (long)gridDim.x * blockDim.x;
    float4 z = make_float4(0.f, 0.f, 0.f, 0.f);
    for (; i < n4; i += stride) out[i] = z;
}

// ---- preprocess W1 -> fp16 fragment image (XOR-swizzled SMEM stage) -----
// grid: (128 kg of 32 k-rows) x (16 ng of 256 n-cols)
__global__ __launch_bounds__(256) void k_preB(const float *__restrict__ W1) {
    __shared__ float s[32][256];
    int kg = blockIdx.x, ng = blockIdx.y, tid = threadIdx.x;
    for (int i = tid; i < 2048; i += 256) {
        int row = i >> 6, c4 = (i & 63) * 4;
        float4 v = *(const float4 *)&W1[(size_t)(kg * 32 + row) * N + ng * 256 + c4];
        *(float4 *)&s[row][c4 ^ ((row & 7) << 2)] = v;
    }
    __syncthreads();
#pragma unroll
    for (int it = 0; it < 16; ++it) {
        int o = tid + it * 256;
        int ntl = o >> 7;
        int rem = o & 127;
        int ktl = rem >> 6;
        int lane = (rem >> 1) & 31;
        int reg = o & 1;
        int g = lane >> 2, t4 = lane & 3;
        int k0 = ktl * 16 + 2 * t4 + reg * 8;
        int n = ntl * 8 + g;
        float a = s[k0][n ^ ((k0 & 7) << 2)];
        float b = s[k0 + 1][n ^ (((k0 + 1) & 7) << 2)];
        g_B[((((size_t)(ng * 32 + ntl)) * 256 + kg * 2 + ktl) * 32 + lane) * 2 + reg] =
            pack_h2(a, b);
    }
}

// ---- preprocess W2 -> fp16 fragment image (direct gmem gather) ----------
// grid: (256 mt of 16 rows) x (8 kg of 32 ktiles)
__global__ __launch_bounds__(256) void k_preA(const float *__restrict__ W2) {
    int mt = blockIdx.x, kg = blockIdx.y, tid = threadIdx.x;
    size_t base = ((size_t)mt * 256 + kg * 32) * 128;
#pragma unroll
    for (int it = 0; it < 16; ++it) {
        int o = tid + it * 256;
        int ktl = o >> 7;
        int rem = o & 127;
        int lane = rem >> 2;
        int reg = rem & 3;
        int g = lane >> 2, t4 = lane & 3;
        int row = mt * 16 + g + (reg & 1) * 8;
        int col = kg * 512 + ktl * 16 + 2 * t4 + (reg >> 1) * 8;
        float2 v = *(const float2 *)&W2[(size_t)row * N + col];
        g_A[base + o] = pack_h2(v.x, v.y);
    }
}

// ---------------- main GEMM: r = rowsum(|W2@W1| * h), fp16 mma.sync ------
// 3-stage cp.async pipeline, K=64 per stage, BM=BN=128, 8 warps (2m x 4n)
#define STG_BYTES 32768        /* A 16K + B 16K */
#define GS_H   (3 * STG_BYTES)
#define GS_RED (GS_H + 512)
#define GSMEM  (GS_RED + 2048)

__device__ __forceinline__ void issue_stage(int s, int mb, int nb,
                                            uint32_t st, int tid) {
    // A: [8 mt][4 ktile][32 lane][4 reg] u32 -> 16 KB
    int mt = tid >> 5, ia = tid & 31;
    const uint32_t *srcA = &g_A[(((size_t)(mb * 8 + mt) * 256 + s * 4) * 32) * 4];
    uint32_t dA = st + mt * 2048;
#pragma unroll
    for (int r = 0; r < 4; ++r)
        cpasync16(dA + r * 512 + ia * 16, srcA + r * 128 + ia * 4);
    // B: [16 nt][4 ktile][32 lane][2 reg] u32 -> 16 KB
    int nt = tid >> 4, ib = tid & 15;
    const uint32_t *srcB = &g_B[(((size_t)(nb * 16 + nt) * 256 + s * 4) * 32) * 2];
    uint32_t dB = st + 16384 + nt * 1024;
#pragma unroll
    for (int r = 0; r < 4; ++r)
        cpasync16(dB + r * 256 + ib * 16, srcB + r * 64 + ib * 4);
    asm volatile("cp.async.commit_group;" ::: "memory");
}

__global__ __launch_bounds__(256, 2) void k_gemm(const float *__restrict__ lb0,
                                                 const float *__restrict__ ub0) {
    extern __shared__ __align__(16) char sm[];
    uint32_t sb = smem_u32(sm);
    const int tid = threadIdx.x, lane = tid & 31, wid = tid >> 5;
    const int wn = wid & 3, wm = wid >> 2;
    const int nb = blockIdx.x, mb = blockIdx.y;
    float *h = (float *)(sm + GS_H);
    float *red = (float *)(sm + GS_RED);
    if (tid < 128) h[tid] = 0.5f * (ub0[nb * 128 + tid] - lb0[nb * 128 + tid]);

    float acc[4][4][4];
#pragma unroll
    for (int a = 0; a < 4; ++a)
#pragma unroll
        for (int b = 0; b < 4; ++b)
#pragma unroll
            for (int c = 0; c < 4; ++c) acc[a][b][c] = 0.f;

    issue_stage(0, mb, nb, sb + 0 * STG_BYTES, tid);
    issue_stage(1, mb, nb, sb + 1 * STG_BYTES, tid);

    for (int s = 0; s < NSTG; ++s) {
        if (s + 2 < NSTG) {
            issue_stage(s + 2, mb, nb, sb + ((s + 2) % 3) * STG_BYTES, tid);
            asm volatile("cp.async.wait_group 2;" ::: "memory");
        } else if (s + 1 < NSTG) {
            asm volatile("cp.async.wait_group 1;" ::: "memory");
        } else {
            asm volatile("cp.async.wait_group 0;" ::: "memory");
        }
        __syncthreads();
        uint32_t st = sb + (s % 3) * STG_BYTES;
        uint32_t aBase = st, bBase = st + 16384;
#pragma unroll
        for (int kk = 0; kk < 4; ++kk) {
            uint32_t af[4][4], bf[4][2];
#pragma unroll
            for (int mt = 0; mt < 4; ++mt)
                lds128(af[mt], aBase + (((wm * 4 + mt) * 4 + kk) * 32 + lane) * 16);
#pragma unroll
            for (int nt = 0; nt < 4; ++nt)
                lds64(bf[nt], bBase + (((wn * 4 + nt) * 4 + kk) * 32 + lane) * 8);
#pragma unroll
            for (int mt = 0; mt < 4; ++mt)
#pragma unroll
                for (int nt = 0; nt < 4; ++nt)
                    mma16(acc[mt][nt], af[mt], bf[nt]);
        }
        __syncthreads();
    }

    // epilogue: weighted abs row-reduction
    const int tig = lane & 3, gp = lane >> 2;
#pragma unroll
    for (int mt = 0; mt < 4; ++mt)
#pragma unroll
        for (int hf = 0; hf < 2; ++hf) {
            float p = 0.f;
#pragma unroll
            for (int nt = 0; nt < 4; ++nt) {
                int n0 = wn * 32 + nt * 8 + 2 * tig;
                p += fabsf(acc[mt][nt][hf * 2 + 0]) * h[n0] +
                     fabsf(acc[mt][nt][hf * 2 + 1]) * h[n0 + 1];
            }
            p += __shfl_xor_sync(0xffffffffu, p, 1);
            p += __shfl_xor_sync(0xffffffffu, p, 2);
            if (tig == 0)
                red[(wm * 64 + mt * 16 + hf * 8 + gp) * 4 + wn] = p;
        }
    __syncthreads();
    if (tid < 128) {
        float v = red[tid * 4 + 0] + red[tid * 4 + 1] + red[tid * 4 + 2] + red[tid * 4 + 3];
        g_rpart[nb][mb * 128 + tid] = v;
    }
}

// ---------------- matvec: t = W1 @ c,  c = (lb0+ub0)/2 -------------------
__global__ void k_t(const float *__restrict__ W1, const float *__restrict__ lb0,
                    const float *__restrict__ ub0) {
    int row = blockIdx.x;
    __shared__ float sred[256];
    const float4 *w = (const float4 *)(W1 + (size_t)row * N);
    const float4 *l4 = (const float4 *)lb0;
    const float4 *u4 = (const float4 *)ub0;
    float s = 0.f;
    for (int c = threadIdx.x; c < N / 4; c += 256) {
        float4 wv = w[c], lv = l4[c], uv = u4[c];
        s += wv.x * (0.5f * (lv.x + uv.x)) + wv.y * (0.5f * (lv.y + uv.y)) +
             wv.z * (0.5f * (lv.z + uv.z)) + wv.w * (0.5f * (lv.w + uv.w));
    }
    sred[threadIdx.x] = s;
    __syncthreads();
    for (int off = 128; off > 0; off >>= 1) {
        if (threadIdx.x < off) sred[threadIdx.x] += sred[threadIdx.x + off];
        __syncthreads();
    }
    if (threadIdx.x == 0) g_t[row] = sred[0];
}

// ---------------- matvec: mc = W2 @ t ; cint = W2 @ b1 + b2 --------------
__global__ void k_w2(const float *__restrict__ W2, const float *__restrict__ b1,
                     const float *__restrict__ b2) {
    int row = blockIdx.x;
    __shared__ float sred[512];
    const float4 *w = (const float4 *)(W2 + (size_t)row * N);
    const float4 *t4 = (const float4 *)g_t;
    const float4 *b4 = (const float4 *)b1;
    float s0 = 0.f, s1 = 0.f;
    for (int c = threadIdx.x; c < N / 4; c += 256) {
        float4 wv = w[c], tv = t4[c], bv = b4[c];
        s0 += wv.x * tv.x + wv.y * tv.y + wv.z * tv.z + wv.w * tv.w;
        s1 += wv.x * bv.x + wv.y * bv.y + wv.z * bv.z + wv.w * bv.w;
    }
    sred[threadIdx.x] = s0;
    sred[256 + threadIdx.x] = s1;
    __syncthreads();
    for (int off = 128; off > 0; off >>= 1) {
        if (threadIdx.x < off) {
            sred[threadIdx.x] += sred[threadIdx.x + off];
            sred[256 + threadIdx.x] += sred[256 + threadIdx.x + off];
        }
        __syncthreads();
    }
    if (threadIdx.x == 0) {
        g_mc[row] = sred[0];
        g_cint[row] = sred[256] + b2[row];
    }
}

// ---------------- finalize: DeepPoly ReLU transformer + scatter ----------
__global__ void k_finalize(const float *__restrict__ raw_alpha,
                           float *__restrict__ out) {
    int i = blockIdx.x * blockDim.x + threadIdx.x;
    if (i >= N) return;
    float r = 0.f;
#pragma unroll
    for (int s = 0; s < 32; ++s) r += g_rpart[s][i];
    float mid = g_mc[i] + g_cint[i];
    float lb = mid - r;
    float ub = mid + r;
    float denom = ub - lb;
    float rs = (denom == 0.f) ? 0.f : ub / denom;
    float rint = (1.f - rs) * ub;
    bool below = (ub <= 0.f);
    bool above = (lb >= 0.f);
    bool crossing = !(below || above);
    float base = above ? 1.f : 0.f;
    float uslope = crossing ? rs : base;
    float uint_ = crossing ? rint : 0.f;
    float v1 = crossing ? 0.f : base;
    float v2 = crossing ? 1.f : base;
    float alpha = 1.f / (1.f + expf(-raw_alpha[i]));
    float lslope = alpha * v1 + (1.f - alpha) * v2;

    const long NN = (long)N * N;
    out[(long)i * N + i] = lslope;               // diag(lslope)
    /* lintercept stays zero */
    out[NN + N + (long)i * N + i] = uslope;      // diag(uslope)
    out[2 * NN + N + i] = uint_;                 // uintercept
}

// --------------------------------------------------------------------------
extern "C" void kernel_launch(void *const *d_in, const int *in_sizes, int n_in,
                              void *d_out, int out_size) {
    const float *raw_alpha = (const float *)d_in[0];
    const float *lb0 = (const float *)d_in[1];
    const float *ub0 = (const float *)d_in[2];
    const float *W1 = (const float *)d_in[3];
    const float *b1 = (const float *)d_in[4];
    const float *W2 = (const float *)d_in[5];
    const float *b2 = (const float *)d_in[6];
    float *out = (float *)d_out;

    cudaFuncSetAttribute(k_gemm, cudaFuncAttributeMaxDynamicSharedMemorySize, GSMEM);

    // order chosen so k_gemm lands at launch index 3 (ncu capture slot)
    dim3 gb(128, 16);
    k_preB<<<gb, 256>>>(W1);
    dim3 ga(256, 8);
    k_preA<<<ga, 256>>>(W2);
    k_zero<<<2048, 256>>>((float4 *)out, (long)out_size / 4);
    dim3 gg(32, 32);
    k_gemm<<<gg, 256, GSMEM>>>(lb0, ub0);
    k_t<<<N, 256>>>(W1, lb0, ub0);
    k_w2<<<N, 256>>>(W2, b1, b2);
    k_finalize<<<N / 256, 256>>>(raw_alpha, out);
}